// round 3
// baseline (speedup 1.0000x reference)
#include <cuda_runtime.h>
#include <cstdint>

#define DI      8192
#define DO      8192
#define NB      1024
#define FAN     16
#define NNZ     (DI * FAN)          // 131072
#define BT      4                   // batch rows per CTA tile (float4 lanes)
#define NBT     (NB / BT)           // 256 batch tiles
#define JCHUNK  512                 // j's per fine work unit (1 per thread)
#define NJC     (DO / JCHUNK)       // 16 j-chunks per btile
#define UNITS   (NBT * NJC)         // 4096 fine units
#define THREADS 512
#define SMEM_BYTES (DI * 16)        // 8192 float4 = 128 KB

// Scratch (no allocation allowed): fixed-degree index table.
// g_idx[j*16 + s] = swizzled pre-index (float4 slot) of the s-th edge into j.
__device__ __align__(16) unsigned short g_idx[DO * FAN];
// Modular slot counter: each launch adds exactly FAN per j, so
// (atomicAdd & 15) enumerates slots 0..15 uniquely per launch — NO reset pass.
__device__ unsigned g_cnt[DO];

__device__ __forceinline__ unsigned swz(unsigned i) {
    // XOR swizzle on float4 index: makes the transpose-store phase conflict-free.
    return i ^ ((i >> 3) & 7u);
}

__global__ void build_kernel(const int* __restrict__ pre,
                             const int* __restrict__ post) {
    int e0 = (blockIdx.x * blockDim.x + threadIdx.x) * 4;
    int4 jj = *reinterpret_cast<const int4*>(post + e0);
    int4 ii = *reinterpret_cast<const int4*>(pre + e0);
    int j[4] = {jj.x, jj.y, jj.z, jj.w};
    int i[4] = {ii.x, ii.y, ii.z, ii.w};
    #pragma unroll
    for (int k = 0; k < 4; ++k) {
        unsigned s = atomicAdd(&g_cnt[j[k]], 1u) & 15u;
        g_idx[j[k] * FAN + s] = (unsigned short)swz((unsigned)i[k]);
    }
}

// Bank-aware slot assignment: put an edge with bank-group (j+s)&7 into slot s
// when possible, so 8 consecutive lanes (consecutive j's) read 8 distinct
// bank-groups at every slot -> near-conflict-free LDS.128.
__global__ void reorder_kernel() {
    int j = blockIdx.x * blockDim.x + threadIdx.x;   // 8192 threads
    uint4* p = reinterpret_cast<uint4*>(&g_idx[j * FAN]);
    uint4 A = p[0], B = p[1];
    unsigned w[8] = {A.x, A.y, A.z, A.w, B.x, B.y, B.z, B.w};

    unsigned short e[FAN];
    #pragma unroll
    for (int k = 0; k < FAN; ++k)
        e[k] = (unsigned short)((w[k >> 1] >> ((k & 1) * 16)) & 0xFFFFu);

    unsigned short out[FAN];
    unsigned used = 0, filled = 0;
    #pragma unroll
    for (int s = 0; s < FAN; ++s) {
        unsigned d = ((unsigned)j + s) & 7u;
        #pragma unroll
        for (int k = 0; k < FAN; ++k) {
            if (!((used >> k) & 1u) && ((e[k] & 7u) == d) && !((filled >> s) & 1u)) {
                out[s] = e[k];
                used |= 1u << k;
                filled |= 1u << s;
            }
        }
    }
    int k = 0;
    #pragma unroll
    for (int s = 0; s < FAN; ++s) {
        if (!((filled >> s) & 1u)) {
            while ((used >> k) & 1u) ++k;
            out[s] = e[k];
            used |= 1u << k;
        }
    }

    unsigned o[8];
    #pragma unroll
    for (int q = 0; q < 8; ++q)
        o[q] = (unsigned)out[2 * q] | ((unsigned)out[2 * q + 1] << 16);
    p[0] = make_uint4(o[0], o[1], o[2], o[3]);
    p[1] = make_uint4(o[4], o[5], o[6], o[7]);
}

__global__ void __launch_bounds__(THREADS, 1)
gather_kernel(const float* __restrict__ x, float* __restrict__ y, int ncta) {
    extern __shared__ float4 xs[];   // xs[swz(i)] = 100*{x[b0][i],...,x[b3][i]}

    unsigned xs_base;
    asm("{ .reg .u64 t; cvta.to.shared.u64 t, %1; cvt.u32.u64 %0, t; }"
        : "=r"(xs_base) : "l"(xs));

    const uint4* idx4 = reinterpret_cast<const uint4*>(g_idx);

    // Contiguous static range of fine units for this CTA.
    int u0 = (int)(((long long)blockIdx.x       * UNITS) / ncta);
    int u1 = (int)(((long long)(blockIdx.x + 1) * UNITS) / ncta);

    int curb = -1;
    for (int u = u0; u < u1; ++u) {
        int b  = u >> 4;          // NJC = 16
        int jc = u & 15;
        int b0 = b * BT;

        if (b != curb) {
            if (curb >= 0) __syncthreads();   // everyone done with old tile
            // ---- Stage + transpose 4 batch rows (scaled by 100), swizzled ----
            const float4* r0 = reinterpret_cast<const float4*>(x + (size_t)(b0 + 0) * DI);
            const float4* r1 = reinterpret_cast<const float4*>(x + (size_t)(b0 + 1) * DI);
            const float4* r2 = reinterpret_cast<const float4*>(x + (size_t)(b0 + 2) * DI);
            const float4* r3 = reinterpret_cast<const float4*>(x + (size_t)(b0 + 3) * DI);
            #pragma unroll
            for (int t = threadIdx.x; t < DI / 4; t += THREADS) {
                float4 v0 = r0[t], v1 = r1[t], v2 = r2[t], v3 = r3[t];
                unsigned i = (unsigned)t * 4u;
                xs[swz(i + 0)] = make_float4(100.f*v0.x, 100.f*v1.x, 100.f*v2.x, 100.f*v3.x);
                xs[swz(i + 1)] = make_float4(100.f*v0.y, 100.f*v1.y, 100.f*v2.y, 100.f*v3.y);
                xs[swz(i + 2)] = make_float4(100.f*v0.z, 100.f*v1.z, 100.f*v2.z, 100.f*v3.z);
                xs[swz(i + 3)] = make_float4(100.f*v0.w, 100.f*v1.w, 100.f*v2.w, 100.f*v3.w);
            }
            __syncthreads();
            curb = b;
        }

        // ---- Gather: 1 j per thread in this unit ----
        int j = jc * JCHUNK + threadIdx.x;
        uint4 A = idx4[2 * j];
        uint4 B = idx4[2 * j + 1];

        // two independent accumulation chains (even/odd words)
        unsigned long long a01 = 0ull, a23 = 0ull;
        unsigned long long b01 = 0ull, b23 = 0ull;
        unsigned words[8] = {A.x, A.y, A.z, A.w, B.x, B.y, B.z, B.w};

        #pragma unroll
        for (int w = 0; w < 8; ++w) {
            unsigned v  = words[w];
            unsigned p0 = xs_base + (v & 0xFFFFu) * 16u;
            unsigned p1 = xs_base + (v >> 16)     * 16u;

            unsigned long long u01, u23, v01, v23;
            asm volatile(
                "{\n\t.reg .b32 a,b,c,d;\n\t"
                "ld.shared.v4.b32 {a,b,c,d},[%2];\n\t"
                "mov.b64 %0,{a,b};\n\t"
                "mov.b64 %1,{c,d};\n\t}"
                : "=l"(u01), "=l"(u23) : "r"(p0));
            asm volatile(
                "{\n\t.reg .b32 a,b,c,d;\n\t"
                "ld.shared.v4.b32 {a,b,c,d},[%2];\n\t"
                "mov.b64 %0,{a,b};\n\t"
                "mov.b64 %1,{c,d};\n\t}"
                : "=l"(v01), "=l"(v23) : "r"(p1));

            // packed fp32 adds — ptxas never fuses these from C++
            asm("add.rn.f32x2 %0,%0,%1;" : "+l"(a01) : "l"(u01));
            asm("add.rn.f32x2 %0,%0,%1;" : "+l"(a23) : "l"(u23));
            asm("add.rn.f32x2 %0,%0,%1;" : "+l"(b01) : "l"(v01));
            asm("add.rn.f32x2 %0,%0,%1;" : "+l"(b23) : "l"(v23));
        }

        asm("add.rn.f32x2 %0,%0,%1;" : "+l"(a01) : "l"(b01));
        asm("add.rn.f32x2 %0,%0,%1;" : "+l"(a23) : "l"(b23));

        float f0, f1, f2, f3;
        asm("mov.b64 {%0,%1},%2;" : "=f"(f0), "=f"(f1) : "l"(a01));
        asm("mov.b64 {%0,%1},%2;" : "=f"(f2), "=f"(f3) : "l"(a23));

        y[(size_t)(b0 + 0) * DO + j] = f0;
        y[(size_t)(b0 + 1) * DO + j] = f1;
        y[(size_t)(b0 + 2) * DO + j] = f2;
        y[(size_t)(b0 + 3) * DO + j] = f3;
    }
}

extern "C" void kernel_launch(void* const* d_in, const int* in_sizes, int n_in,
                              void* d_out, int out_size) {
    const float* x    = (const float*)d_in[0];
    const int*   pre  = (const int*)d_in[1];
    const int*   post = (const int*)d_in[2];
    float*       y    = (float*)d_out;

    (void)in_sizes; (void)n_in; (void)out_size;

    int nsm = 0;
    cudaDeviceGetAttribute(&nsm, cudaDevAttrMultiProcessorCount, 0);
    if (nsm <= 0) nsm = 148;

    cudaFuncSetAttribute(gather_kernel,
                         cudaFuncAttributeMaxDynamicSharedMemorySize, SMEM_BYTES);

    build_kernel<<<NNZ / (256 * 4), 256>>>(pre, post);
    reorder_kernel<<<DO / 256, 256>>>();
    gather_kernel<<<nsm, THREADS, SMEM_BYTES>>>(x, y, nsm);
}

// round 4
// speedup vs baseline: 1.1511x; 1.1511x over previous
#include <cuda_runtime.h>
#include <cstdint>

#define DI      8192
#define DO      8192
#define NB      1024
#define FAN     16
#define NNZ     (DI * FAN)          // 131072
#define BT      4                   // batch rows per CTA tile (float4 lanes)
#define NBT     (NB / BT)           // 256 batch tiles
#define JCHUNK  512                 // j's per fine work unit (1 per thread)
#define NJC     (DO / JCHUNK)       // 16 j-chunks per btile
#define UNITS   (NBT * NJC)         // 4096 fine units
#define THREADS 512
#define SMEM_BYTES (DI * 16)        // 8192 float4 = 128 KB

// Scratch (no allocation allowed): fixed-degree index table.
// g_idx[j*16 + s] = swizzled pre-index (float4 slot) of the s-th edge into j.
__device__ __align__(16) unsigned short g_idx[DO * FAN];
// Modular slot counter: each launch adds exactly FAN per j, so
// (atomicAdd & 15) enumerates slots 0..15 uniquely per launch — NO reset pass.
__device__ unsigned g_cnt[DO];

__device__ __forceinline__ unsigned swz(unsigned i) {
    // XOR swizzle on float4 index: makes the transpose-store phase conflict-free.
    return i ^ ((i >> 3) & 7u);
}

__global__ void build_kernel(const int* __restrict__ pre,
                             const int* __restrict__ post) {
    int e0 = (blockIdx.x * blockDim.x + threadIdx.x) * 4;
    int4 jj = *reinterpret_cast<const int4*>(post + e0);
    int4 ii = *reinterpret_cast<const int4*>(pre + e0);
    int j[4] = {jj.x, jj.y, jj.z, jj.w};
    int i[4] = {ii.x, ii.y, ii.z, ii.w};
    #pragma unroll
    for (int k = 0; k < 4; ++k) {
        unsigned s = atomicAdd(&g_cnt[j[k]], 1u) & 15u;
        g_idx[j[k] * FAN + s] = (unsigned short)swz((unsigned)i[k]);
    }
}

__global__ void __launch_bounds__(THREADS, 1)
gather_kernel(const float* __restrict__ x, float* __restrict__ y, int ncta) {
    extern __shared__ float4 xs[];   // xs[swz(i)] = 100*{x[b0][i],...,x[b3][i]}

    const uint4* idx4 = reinterpret_cast<const uint4*>(g_idx);

    // Contiguous static range of fine units for this CTA.
    int u0 = (int)(((long long)blockIdx.x       * UNITS) / ncta);
    int u1 = (int)(((long long)(blockIdx.x + 1) * UNITS) / ncta);

    int curb = -1;
    for (int u = u0; u < u1; ++u) {
        int b  = u >> 4;          // NJC = 16
        int jc = u & 15;
        int b0 = b * BT;

        if (b != curb) {
            if (curb >= 0) __syncthreads();   // everyone done with old tile
            // ---- Stage + transpose 4 batch rows (scaled by 100), swizzled ----
            const float4* r0 = reinterpret_cast<const float4*>(x + (size_t)(b0 + 0) * DI);
            const float4* r1 = reinterpret_cast<const float4*>(x + (size_t)(b0 + 1) * DI);
            const float4* r2 = reinterpret_cast<const float4*>(x + (size_t)(b0 + 2) * DI);
            const float4* r3 = reinterpret_cast<const float4*>(x + (size_t)(b0 + 3) * DI);
            #pragma unroll
            for (int t = threadIdx.x; t < DI / 4; t += THREADS) {
                float4 v0 = r0[t], v1 = r1[t], v2 = r2[t], v3 = r3[t];
                unsigned i = (unsigned)t * 4u;
                xs[swz(i + 0)] = make_float4(100.f*v0.x, 100.f*v1.x, 100.f*v2.x, 100.f*v3.x);
                xs[swz(i + 1)] = make_float4(100.f*v0.y, 100.f*v1.y, 100.f*v2.y, 100.f*v3.y);
                xs[swz(i + 2)] = make_float4(100.f*v0.z, 100.f*v1.z, 100.f*v2.z, 100.f*v3.z);
                xs[swz(i + 3)] = make_float4(100.f*v0.w, 100.f*v1.w, 100.f*v2.w, 100.f*v3.w);
            }
            __syncthreads();
            curb = b;
        }

        // ---- Gather: 1 j per thread; plain C++ loads so ptxas can
        //      front-batch the 16 LDS.128 for high MLP ----
        int j = jc * JCHUNK + threadIdx.x;
        uint4 A = idx4[2 * j];
        uint4 B = idx4[2 * j + 1];

        unsigned s[16];
        s[0]  = A.x & 0xFFFFu;  s[1]  = A.x >> 16;
        s[2]  = A.y & 0xFFFFu;  s[3]  = A.y >> 16;
        s[4]  = A.z & 0xFFFFu;  s[5]  = A.z >> 16;
        s[6]  = A.w & 0xFFFFu;  s[7]  = A.w >> 16;
        s[8]  = B.x & 0xFFFFu;  s[9]  = B.x >> 16;
        s[10] = B.y & 0xFFFFu;  s[11] = B.y >> 16;
        s[12] = B.z & 0xFFFFu;  s[13] = B.z >> 16;
        s[14] = B.w & 0xFFFFu;  s[15] = B.w >> 16;

        // 8 independent accumulation chains (2 per batch lane).
        float a0 = 0.f, a1 = 0.f, a2 = 0.f, a3 = 0.f;
        float c0 = 0.f, c1 = 0.f, c2 = 0.f, c3 = 0.f;

        #pragma unroll
        for (int w = 0; w < 16; w += 2) {
            float4 g = xs[s[w]];
            float4 h = xs[s[w + 1]];
            a0 += g.x; a1 += g.y; a2 += g.z; a3 += g.w;
            c0 += h.x; c1 += h.y; c2 += h.z; c3 += h.w;
        }

        y[(size_t)(b0 + 0) * DO + j] = a0 + c0;
        y[(size_t)(b0 + 1) * DO + j] = a1 + c1;
        y[(size_t)(b0 + 2) * DO + j] = a2 + c2;
        y[(size_t)(b0 + 3) * DO + j] = a3 + c3;
    }
}

extern "C" void kernel_launch(void* const* d_in, const int* in_sizes, int n_in,
                              void* d_out, int out_size) {
    const float* x    = (const float*)d_in[0];
    const int*   pre  = (const int*)d_in[1];
    const int*   post = (const int*)d_in[2];
    float*       y    = (float*)d_out;

    (void)in_sizes; (void)n_in; (void)out_size;

    int nsm = 0;
    cudaDeviceGetAttribute(&nsm, cudaDevAttrMultiProcessorCount, 0);
    if (nsm <= 0) nsm = 148;

    cudaFuncSetAttribute(gather_kernel,
                         cudaFuncAttributeMaxDynamicSharedMemorySize, SMEM_BYTES);

    build_kernel<<<NNZ / (256 * 4), 256>>>(pre, post);
    gather_kernel<<<nsm, THREADS, SMEM_BYTES>>>(x, y, nsm);
}

// round 5
// speedup vs baseline: 1.7164x; 1.4912x over previous
#include <cuda_runtime.h>
#include <cuda_fp16.h>
#include <cstdint>

#define DI      8192
#define DO      8192
#define NB      1024
#define FAN     16
#define NNZ     (DI * FAN)          // 131072
#define BT      8                   // batch rows per CTA tile (8 halves = 16B)
#define NBT     (NB / BT)           // 128 batch tiles
#define JCHUNK  512                 // j's per fine work unit (1 per thread)
#define NJC     (DO / JCHUNK)       // 16 j-chunks per btile
#define UNITS   (NBT * NJC)         // 2048 fine units
#define THREADS 512
#define SMEM_BYTES (DI * 16)        // 8192 slots x 16B = 128 KB

// Scratch (no allocation allowed): fixed-degree index table.
// g_idx[j*16 + s] = swizzled slot index of the s-th edge into output j.
__device__ __align__(16) unsigned short g_idx[DO * FAN];
// Modular slot counter: each launch adds exactly FAN per j, so
// (atomicAdd & 15) enumerates slots 0..15 uniquely per launch — NO reset pass.
__device__ unsigned g_cnt[DO];

__device__ __forceinline__ unsigned swz(unsigned i) {
    // XOR swizzle on 16B slot index: staging stores hit each bank-group
    // exactly 4x per warp = the 4-wavefront minimum (conflict-free).
    return i ^ ((i >> 3) & 7u);
}

__global__ void build_kernel(const int* __restrict__ pre,
                             const int* __restrict__ post) {
    int e0 = (blockIdx.x * blockDim.x + threadIdx.x) * 4;
    int4 jj = *reinterpret_cast<const int4*>(post + e0);
    int4 ii = *reinterpret_cast<const int4*>(pre + e0);
    int j[4] = {jj.x, jj.y, jj.z, jj.w};
    int i[4] = {ii.x, ii.y, ii.z, ii.w};
    #pragma unroll
    for (int k = 0; k < 4; ++k) {
        unsigned s = atomicAdd(&g_cnt[j[k]], 1u) & 15u;
        g_idx[j[k] * FAN + s] = (unsigned short)swz((unsigned)i[k]);
    }
}

__device__ __forceinline__ unsigned h2bits(__half2 h) {
    return *reinterpret_cast<unsigned*>(&h);
}
__device__ __forceinline__ __half2 bits2h(unsigned u) {
    return *reinterpret_cast<__half2*>(&u);
}

__global__ void __launch_bounds__(THREADS, 1)
gather_kernel(const float* __restrict__ x, float* __restrict__ y, int ncta) {
    extern __shared__ uint4 xs[];   // xs[swz(i)] = fp16 {100*x[b0..b7][i]}

    // Contiguous static range of fine units for this CTA.
    int u0 = (int)(((long long)blockIdx.x       * UNITS) / ncta);
    int u1 = (int)(((long long)(blockIdx.x + 1) * UNITS) / ncta);

    const uint4* idx4 = reinterpret_cast<const uint4*>(g_idx);

    int curb = -1;
    for (int u = u0; u < u1; ++u) {
        int b  = u >> 4;          // NJC = 16
        int jc = u & 15;
        int b0 = b * BT;

        if (b != curb) {
            if (curb >= 0) __syncthreads();   // everyone done with old tile
            // ---- Stage 8 batch rows as fp16 (scaled by 100), transposed+swizzled ----
            const float4* r[BT];
            #pragma unroll
            for (int q = 0; q < BT; ++q)
                r[q] = reinterpret_cast<const float4*>(x + (size_t)(b0 + q) * DI);

            for (int t = threadIdx.x; t < DI / 4; t += THREADS) {
                float4 v[BT];
                #pragma unroll
                for (int q = 0; q < BT; ++q) v[q] = r[q][t];
                unsigned i = (unsigned)t * 4u;
                #pragma unroll
                for (int c = 0; c < 4; ++c) {
                    float e[BT];
                    e[0] = (&v[0].x)[c]; e[1] = (&v[1].x)[c];
                    e[2] = (&v[2].x)[c]; e[3] = (&v[3].x)[c];
                    e[4] = (&v[4].x)[c]; e[5] = (&v[5].x)[c];
                    e[6] = (&v[6].x)[c]; e[7] = (&v[7].x)[c];
                    uint4 o;
                    o.x = h2bits(__float22half2_rn(make_float2(100.f*e[0], 100.f*e[1])));
                    o.y = h2bits(__float22half2_rn(make_float2(100.f*e[2], 100.f*e[3])));
                    o.z = h2bits(__float22half2_rn(make_float2(100.f*e[4], 100.f*e[5])));
                    o.w = h2bits(__float22half2_rn(make_float2(100.f*e[6], 100.f*e[7])));
                    xs[swz(i + c)] = o;
                }
            }
            __syncthreads();
            curb = b;
        }

        // ---- Gather: 1 j per thread; 16 x LDS.128, pair edges with HADD2,
        //      convert pair-sums to fp32 and accumulate in fp32 ----
        int j = jc * JCHUNK + threadIdx.x;
        uint4 A = idx4[2 * j];
        uint4 B = idx4[2 * j + 1];

        unsigned s[16];
        s[0]  = A.x & 0xFFFFu;  s[1]  = A.x >> 16;
        s[2]  = A.y & 0xFFFFu;  s[3]  = A.y >> 16;
        s[4]  = A.z & 0xFFFFu;  s[5]  = A.z >> 16;
        s[6]  = A.w & 0xFFFFu;  s[7]  = A.w >> 16;
        s[8]  = B.x & 0xFFFFu;  s[9]  = B.x >> 16;
        s[10] = B.y & 0xFFFFu;  s[11] = B.y >> 16;
        s[12] = B.z & 0xFFFFu;  s[13] = B.z >> 16;
        s[14] = B.w & 0xFFFFu;  s[15] = B.w >> 16;

        float a0=0.f,a1=0.f,a2=0.f,a3=0.f,a4=0.f,a5=0.f,a6=0.f,a7=0.f;

        #pragma unroll
        for (int p = 0; p < 8; ++p) {
            uint4 va = xs[s[2*p]];
            uint4 vb = xs[s[2*p + 1]];
            __half2 h0 = __hadd2(bits2h(va.x), bits2h(vb.x));
            __half2 h1 = __hadd2(bits2h(va.y), bits2h(vb.y));
            __half2 h2 = __hadd2(bits2h(va.z), bits2h(vb.z));
            __half2 h3 = __hadd2(bits2h(va.w), bits2h(vb.w));
            float2 f0 = __half22float2(h0);
            float2 f1 = __half22float2(h1);
            float2 f2 = __half22float2(h2);
            float2 f3 = __half22float2(h3);
            a0 += f0.x; a1 += f0.y; a2 += f1.x; a3 += f1.y;
            a4 += f2.x; a5 += f2.y; a6 += f3.x; a7 += f3.y;
        }

        float* acc = &a0;
        y[(size_t)(b0 + 0) * DO + j] = a0;
        y[(size_t)(b0 + 1) * DO + j] = a1;
        y[(size_t)(b0 + 2) * DO + j] = a2;
        y[(size_t)(b0 + 3) * DO + j] = a3;
        y[(size_t)(b0 + 4) * DO + j] = a4;
        y[(size_t)(b0 + 5) * DO + j] = a5;
        y[(size_t)(b0 + 6) * DO + j] = a6;
        y[(size_t)(b0 + 7) * DO + j] = a7;
        (void)acc;
    }
}

extern "C" void kernel_launch(void* const* d_in, const int* in_sizes, int n_in,
                              void* d_out, int out_size) {
    const float* x    = (const float*)d_in[0];
    const int*   pre  = (const int*)d_in[1];
    const int*   post = (const int*)d_in[2];
    float*       y    = (float*)d_out;

    (void)in_sizes; (void)n_in; (void)out_size;

    int nsm = 0;
    cudaDeviceGetAttribute(&nsm, cudaDevAttrMultiProcessorCount, 0);
    if (nsm <= 0) nsm = 148;

    cudaFuncSetAttribute(gather_kernel,
                         cudaFuncAttributeMaxDynamicSharedMemorySize, SMEM_BYTES);

    build_kernel<<<NNZ / (256 * 4), 256>>>(pre, post);
    gather_kernel<<<nsm, THREADS, SMEM_BYTES>>>(x, y, nsm);
}